// round 7
// baseline (speedup 1.0000x reference)
#include <cuda_runtime.h>

#define B_ 2048
#define K_ 8
#define O_ 256
#define I_ 512
#define TINY_ 1e-10f

#define OT 8                 // o's per tile (32KB smem: mean+sigma)
#define GROUPS (K_ * (O_ / OT))   // 256 (k, o-tile) groups
#define CPG 8                // blocks (chunks) per group -> grid 2048

// Scratch (allocation-free requirement): __device__ globals.
__device__ float4 g_sigma4[K_ * O_ * I_ / 4];   // exp(log_sigma), 4 MB
__device__ int    g_idx[B_];                    // selected component per batch
__device__ int    g_blist[K_ * B_];             // batches compacted by k
__device__ int    g_cnt[K_];                    // count per k

#define SIGMA_BLOCKS ((K_ * O_ * I_ / 4) / 256)   // 1024
#define IDX_BLOCKS   (B_ / 256)                   // 8

// --- Launch 1: sigma = exp(log_sigma)  +  per-batch Gumbel argmax ---------
__global__ void prep_kernel(const float4* __restrict__ log_sigma,
                            const float* __restrict__ u_gumbel,
                            const float* __restrict__ mix_weights) {
    if (blockIdx.x < SIGMA_BLOCKS) {
        int i = blockIdx.x * blockDim.x + threadIdx.x;
        float4 v = log_sigma[i];
        float4 r;
        r.x = __expf(v.x); r.y = __expf(v.y); r.z = __expf(v.z); r.w = __expf(v.w);
        g_sigma4[i] = r;
    } else {
        int b = (blockIdx.x - SIGMA_BLOCKS) * blockDim.x + threadIdx.x;
        float best = -3.402823466e+38f;
        int best_k = 0;
#pragma unroll
        for (int k = 0; k < K_; k++) {
            float u = u_gumbel[b * K_ + k];
            float g = -logf(-logf(u + TINY_) + TINY_);
            float s = mix_weights[k] + g;         // / TAU (=1)
            if (s > best) { best = s; best_k = k; }  // first-index tie-break == jnp.argmax
        }
        g_idx[b] = best_k;
    }
}

// --- Launch 2: compact batch indices by k (order-free, values deterministic)
__global__ void compact_kernel() {
    __shared__ int cnt;
    const int k = blockIdx.x;
    if (threadIdx.x == 0) cnt = 0;
    __syncthreads();
    for (int b = threadIdx.x; b < B_; b += blockDim.x) {
        if (g_idx[b] == k) {
            int p = atomicAdd(&cnt, 1);
            g_blist[k * B_ + p] = b;
        }
    }
    __syncthreads();
    if (threadIdx.x == 0) g_cnt[k] = cnt;
}

// --- Launch 3: out[b,o] = sum_i X[b,i]*(mean[k,o,i] + sigma[k,o,i]*eps[b,o,i])
// Block = (k, 8-o tile, chunk). mean+sigma for the tile staged ONCE in smem,
// reused across all batches of component k. Warp owns one b at a time:
// X row in registers, eps streamed (__ldcs), mean/sigma from smem.
__global__ void __launch_bounds__(256, 4)
bayes_linear_kernel(const float* __restrict__ X,
                    const float* __restrict__ mean,
                    const float* __restrict__ eps,
                    float* __restrict__ out) {
    __shared__ float4 ms[OT * (I_ / 4)];   // 16 KB mean tile
    __shared__ float4 ss[OT * (I_ / 4)];   // 16 KB sigma tile

    const int grp   = blockIdx.x / CPG;          // 0..255
    const int chunk = blockIdx.x % CPG;
    const int k  = grp / (O_ / OT);
    const int o0 = (grp % (O_ / OT)) * OT;

    // Stage mean+sigma tile (32 KB from L2, once per block)
    {
        const float4* mg = (const float4*)(mean + ((size_t)k * O_ + o0) * I_);
        const float4* sg = g_sigma4 + ((size_t)k * O_ + o0) * (I_ / 4);
        for (int t = threadIdx.x; t < OT * (I_ / 4); t += 256) {
            ms[t] = __ldg(mg + t);
            ss[t] = __ldg(sg + t);
        }
    }
    __syncthreads();

    const int warp = threadIdx.x >> 5;
    const int lane = threadIdx.x & 31;
    const int cnt  = g_cnt[k];

    for (int gi = chunk * 8 + warp; gi < cnt; gi += CPG * 8) {
        const int b = g_blist[k * B_ + gi];

        // X row -> registers (L2-resident, 2KB/row)
        const float4* xp = (const float4*)(X + (size_t)b * I_);
        float4 x0 = __ldg(xp + lane);
        float4 x1 = __ldg(xp + 32 + lane);
        float4 x2 = __ldg(xp + 64 + lane);
        float4 x3 = __ldg(xp + 96 + lane);

        const float4* ep = (const float4*)(eps + ((size_t)b * O_ + o0) * I_);
        float* ob = out + (size_t)b * O_ + o0;

#pragma unroll
        for (int oo = 0; oo < OT; oo += 2) {
            const float4* e0p = ep + (size_t)oo * (I_ / 4);
            const float4* e1p = e0p + (I_ / 4);
            const float4* m0p = ms + oo * (I_ / 4);
            const float4* m1p = m0p + (I_ / 4);
            const float4* s0p = ss + oo * (I_ / 4);
            const float4* s1p = s0p + (I_ / 4);

            float acc0 = 0.0f, acc1 = 0.0f;
#pragma unroll
            for (int j = 0; j < 4; j++) {
                const int v = j * 32 + lane;       // coalesced 512B / instr
                float4 e0 = __ldcs(e0p + v);       // streamed once: evict-first
                float4 e1 = __ldcs(e1p + v);
                float4 m0 = m0p[v];
                float4 m1 = m1p[v];
                float4 s0 = s0p[v];
                float4 s1 = s1p[v];
                float4 xv = (j == 0) ? x0 : (j == 1) ? x1 : (j == 2) ? x2 : x3;
                acc0 = fmaf(xv.x, fmaf(s0.x, e0.x, m0.x), acc0);
                acc0 = fmaf(xv.y, fmaf(s0.y, e0.y, m0.y), acc0);
                acc0 = fmaf(xv.z, fmaf(s0.z, e0.z, m0.z), acc0);
                acc0 = fmaf(xv.w, fmaf(s0.w, e0.w, m0.w), acc0);
                acc1 = fmaf(xv.x, fmaf(s1.x, e1.x, m1.x), acc1);
                acc1 = fmaf(xv.y, fmaf(s1.y, e1.y, m1.y), acc1);
                acc1 = fmaf(xv.z, fmaf(s1.z, e1.z, m1.z), acc1);
                acc1 = fmaf(xv.w, fmaf(s1.w, e1.w, m1.w), acc1);
            }
#pragma unroll
            for (int off = 16; off; off >>= 1) {
                acc0 += __shfl_xor_sync(0xFFFFFFFFu, acc0, off);
                acc1 += __shfl_xor_sync(0xFFFFFFFFu, acc1, off);
            }
            if (lane == 0) { ob[oo] = acc0; ob[oo + 1] = acc1; }
        }
    }
}

extern "C" void kernel_launch(void* const* d_in, const int* in_sizes, int n_in,
                              void* d_out, int out_size) {
    const float* X         = (const float*)d_in[0];   // [B, I]
    const float* mixw      = (const float*)d_in[1];   // [K]
    const float* mean      = (const float*)d_in[2];   // [K, O, I]
    const float* log_sigma = (const float*)d_in[3];   // [K, O, I]
    const float* u_gumbel  = (const float*)d_in[4];   // [B, K]
    const float* eps       = (const float*)d_in[5];   // [B, O, I]
    float* out = (float*)d_out;                       // [B, O]

    prep_kernel<<<SIGMA_BLOCKS + IDX_BLOCKS, 256>>>(
        (const float4*)log_sigma, u_gumbel, mixw);
    compact_kernel<<<K_, 256>>>();
    bayes_linear_kernel<<<GROUPS * CPG, 256>>>(X, mean, eps, out);
}